// round 12
// baseline (speedup 1.0000x reference)
#include <cuda_runtime.h>

// Sparse attention: query l attends to keys l-d, d in
//   {0,1,2,3,4,5,6,7,9,13,21,37,69,133,261,517,1029} (clipped at 0).
// B=4, L=2048, H=8, E=D=64. Layouts [B,L,H,E].
// v6: 2 queries/warp. K/V staged in batches of 4 float4 rows so peak live
//     regs fit 48 -> 5 CTAs/SM (occ cap 62.5%). Reduction logic identical
//     to validated v5 (halving tree + mask-8 merge, lane j owns score j).

namespace {
constexpr int Lq = 2048;
constexpr int Hh = 8;
constexpr int Bb = 4;
constexpr int Ee = 64;
}

__global__ __launch_bounds__(256, 5) void sparse_attn_kernel(
    const float* __restrict__ Q,
    const float* __restrict__ Kp,
    const float* __restrict__ Vp,
    float*       __restrict__ O)
{
    const unsigned FULL = 0xffffffffu;
    const int offsB[8] = {9,13,21,37,69,133,261,517};

    const int warp   = threadIdx.x >> 5;
    const int lane   = threadIdx.x & 31;
    const int lane16 = lane & 15;
    const int sub    = lane >> 4;
    const int g      = blockIdx.x * 16 + warp * 2 + sub;

    const int l  = g & (Lq - 1);
    const int bh = g >> 11;
    const int h  = bh & (Hh - 1);
    const int b  = bh >> 3;

    const int rowstride = Hh * Ee;                    // 512 floats
    const int rs4       = rowstride / 4;
    const int base_bh   = b * Lq * rowstride + h * Ee;
    const int qoff      = base_bh + l * rowstride;

    const float4* kbase = reinterpret_cast<const float4*>(Kp + base_bh) + lane16;
    const float4* vbase = reinterpret_cast<const float4*>(Vp + base_bh) + lane16;

    const float4 q = reinterpret_cast<const float4*>(Q + qoff)[lane16];

    float p[8];
    float s16;

    // ---- K window rows (offsets 0..7), two batches of 4 ----
    {
        float4 kb[4];
#pragma unroll
        for (int j = 0; j < 4; ++j) {
            int k = l - j; k = k >= 0 ? k : 0;
            kb[j] = kbase[k * rs4];
        }
#pragma unroll
        for (int j = 0; j < 4; ++j) {
            float t = q.x * kb[j].x;
            t = fmaf(q.y, kb[j].y, t);
            t = fmaf(q.z, kb[j].z, t);
            p[j] = fmaf(q.w, kb[j].w, t);
        }
#pragma unroll
        for (int j = 0; j < 4; ++j) {
            int k = l - (4 + j); k = k >= 0 ? k : 0;
            kb[j] = kbase[k * rs4];
        }
#pragma unroll
        for (int j = 0; j < 4; ++j) {
            float t = q.x * kb[j].x;
            t = fmaf(q.y, kb[j].y, t);
            t = fmaf(q.z, kb[j].z, t);
            p[4 + j] = fmaf(q.w, kb[j].w, t);
        }
    }

    // ---- offset-1029 row: dot + 16-lane butterfly ----
    {
        int k = l - 1029; k = k >= 0 ? k : 0;
        const float4 k16 = kbase[k * rs4];
        float t = q.x * k16.x;
        t = fmaf(q.y, k16.y, t);
        t = fmaf(q.z, k16.z, t);
        s16 = fmaf(q.w, k16.w, t);
#pragma unroll
        for (int m = 8; m; m >>= 1)
            s16 += __shfl_xor_sync(FULL, s16, m);
    }

    // ---- window tree: masks 4,2,1 -> half-sum of score (lane16&7) ----
    float a;
    {
        const bool b2 = lane16 & 4;
#pragma unroll
        for (int i = 0; i < 4; ++i) {
            const float send = b2 ? p[i] : p[i + 4];
            const float r    = __shfl_xor_sync(FULL, send, 4);
            p[i] = (b2 ? p[i + 4] : p[i]) + r;
        }
        const bool b1 = lane16 & 2;
#pragma unroll
        for (int i = 0; i < 2; ++i) {
            const float send = b1 ? p[i] : p[i + 2];
            const float r    = __shfl_xor_sync(FULL, send, 2);
            p[i] = (b1 ? p[i + 2] : p[i]) + r;
        }
        const bool b0 = lane16 & 1;
        const float send = b0 ? p[0] : p[1];
        const float r    = __shfl_xor_sync(FULL, send, 1);
        a = (b0 ? p[1] : p[0]) + r;
    }

    // ---- K log rows (offsets offsB), two batches of 4 ----
    {
        float4 kb[4];
#pragma unroll
        for (int j = 0; j < 4; ++j) {
            int k = l - offsB[j]; k = k >= 0 ? k : 0;
            kb[j] = kbase[k * rs4];
        }
#pragma unroll
        for (int j = 0; j < 4; ++j) {
            float t = q.x * kb[j].x;
            t = fmaf(q.y, kb[j].y, t);
            t = fmaf(q.z, kb[j].z, t);
            p[j] = fmaf(q.w, kb[j].w, t);
        }
#pragma unroll
        for (int j = 0; j < 4; ++j) {
            int k = l - offsB[4 + j]; k = k >= 0 ? k : 0;
            kb[j] = kbase[k * rs4];
        }
#pragma unroll
        for (int j = 0; j < 4; ++j) {
            float t = q.x * kb[j].x;
            t = fmaf(q.y, kb[j].y, t);
            t = fmaf(q.z, kb[j].z, t);
            p[4 + j] = fmaf(q.w, kb[j].w, t);
        }
    }

    // ---- log tree: masks 4,2,1 ----
    float bb;
    {
        const bool b2 = lane16 & 4;
#pragma unroll
        for (int i = 0; i < 4; ++i) {
            const float send = b2 ? p[i] : p[i + 4];
            const float r    = __shfl_xor_sync(FULL, send, 4);
            p[i] = (b2 ? p[i + 4] : p[i]) + r;
        }
        const bool b1 = lane16 & 2;
#pragma unroll
        for (int i = 0; i < 2; ++i) {
            const float send = b1 ? p[i] : p[i + 2];
            const float r    = __shfl_xor_sync(FULL, send, 2);
            p[i] = (b1 ? p[i + 2] : p[i]) + r;
        }
        const bool b0 = lane16 & 1;
        const float send = b0 ? p[0] : p[1];
        const float r    = __shfl_xor_sync(FULL, send, 1);
        bb = (b0 ? p[1] : p[0]) + r;
    }

    // ---- merge halves: lane j (0..15) ends with full score j ----
    float sc;
    {
        const bool hi = lane16 & 8;
        const float send = hi ? a : bb;
        const float r    = __shfl_xor_sync(FULL, send, 8);
        sc = (hi ? bb : a) + r;
    }

    // ---- lane-parallel softmax, no max-subtraction (|s| <~ 6, fp32-safe) ----
    int my_off;
    {
        const int lo[16] = {0,1,2,3,4,5,6,7,9,13,21,37,69,133,261,517};
        my_off = lo[lane16];
    }
    float w = (l >= my_off) ? __expf(sc * 0.125f) : 0.f;
    const float w16 = (l >= 1029) ? __expf(s16 * 0.125f) : 0.f;

    float den = w;
#pragma unroll
    for (int m = 8; m; m >>= 1)
        den += __shfl_xor_sync(FULL, den, m);
    den += w16;
    const float inv = __fdividef(1.f, den);

    // ---- V accumulate: 4-row batches, one float4 buffer ----
    float4 acc = make_float4(0.f, 0.f, 0.f, 0.f);
    {
        float4 vb[4];
        // scores 0..3 (offsets 0..3)
#pragma unroll
        for (int j = 0; j < 4; ++j) {
            int k = l - j; k = k >= 0 ? k : 0;
            vb[j] = vbase[k * rs4];
        }
#pragma unroll
        for (int j = 0; j < 4; ++j) {
            const float wj = __shfl_sync(FULL, w, j, 16);
            acc.x = fmaf(wj, vb[j].x, acc.x);
            acc.y = fmaf(wj, vb[j].y, acc.y);
            acc.z = fmaf(wj, vb[j].z, acc.z);
            acc.w = fmaf(wj, vb[j].w, acc.w);
        }
        // scores 4..7 (offsets 4..7)
#pragma unroll
        for (int j = 0; j < 4; ++j) {
            int k = l - (4 + j); k = k >= 0 ? k : 0;
            vb[j] = vbase[k * rs4];
        }
#pragma unroll
        for (int j = 0; j < 4; ++j) {
            const float wj = __shfl_sync(FULL, w, 4 + j, 16);
            acc.x = fmaf(wj, vb[j].x, acc.x);
            acc.y = fmaf(wj, vb[j].y, acc.y);
            acc.z = fmaf(wj, vb[j].z, acc.z);
            acc.w = fmaf(wj, vb[j].w, acc.w);
        }
        // scores 8..11 (offsets 9,13,21,37)
#pragma unroll
        for (int j = 0; j < 4; ++j) {
            int k = l - offsB[j]; k = k >= 0 ? k : 0;
            vb[j] = vbase[k * rs4];
        }
#pragma unroll
        for (int j = 0; j < 4; ++j) {
            const float wj = __shfl_sync(FULL, w, 8 + j, 16);
            acc.x = fmaf(wj, vb[j].x, acc.x);
            acc.y = fmaf(wj, vb[j].y, acc.y);
            acc.z = fmaf(wj, vb[j].z, acc.z);
            acc.w = fmaf(wj, vb[j].w, acc.w);
        }
        // scores 12..15 (offsets 69,133,261,517)
#pragma unroll
        for (int j = 0; j < 4; ++j) {
            int k = l - offsB[4 + j]; k = k >= 0 ? k : 0;
            vb[j] = vbase[k * rs4];
        }
#pragma unroll
        for (int j = 0; j < 4; ++j) {
            const float wj = __shfl_sync(FULL, w, 12 + j, 16);
            acc.x = fmaf(wj, vb[j].x, acc.x);
            acc.y = fmaf(wj, vb[j].y, acc.y);
            acc.z = fmaf(wj, vb[j].z, acc.z);
            acc.w = fmaf(wj, vb[j].w, acc.w);
        }
        // offset 1029
        {
            int k = l - 1029; k = k >= 0 ? k : 0;
            const float4 v16 = vbase[k * rs4];
            acc.x = fmaf(w16, v16.x, acc.x);
            acc.y = fmaf(w16, v16.y, acc.y);
            acc.z = fmaf(w16, v16.z, acc.z);
            acc.w = fmaf(w16, v16.w, acc.w);
        }
    }

    float4 out;
    out.x = acc.x * inv;
    out.y = acc.y * inv;
    out.z = acc.z * inv;
    out.w = acc.w * inv;
    reinterpret_cast<float4*>(O + qoff)[lane16] = out;
}

extern "C" void kernel_launch(void* const* d_in, const int* in_sizes, int n_in,
                              void* d_out, int out_size)
{
    const float* Q = (const float*)d_in[0];
    const float* K = (const float*)d_in[1];
    const float* V = (const float*)d_in[2];
    float*       O = (float*)d_out;

    const int total_queries = Bb * Hh * Lq;           // 65536
    dim3 grid(total_queries / 16);
    dim3 block(256);
    sparse_attn_kernel<<<grid, block>>>(Q, K, V, O);
}

// round 13
// speedup vs baseline: 1.6127x; 1.6127x over previous
#include <cuda_runtime.h>

// Sparse attention: query l attends to keys l-d, d in
//   {0,1,2,3,4,5,6,7,9,13,21,37,69,133,261,517,1029} (clipped at 0).
// B=4, L=2048, H=8, E=D=64. Layouts [B,L,H,E].
// v7: v5 base (2 adjacent queries/warp, 9/8 load batches, 64 regs) +
//     warp-internal WINDOW ROW SHARING: queries l and l+1 share 7 of 8 window
//     rows; both halves load the same 9-row union (LDG dedups 4wf -> 2wf),
//     then select per-half scores/weights. ~19% fewer L1 wavefronts.

namespace {
constexpr int Lq = 2048;
constexpr int Hh = 8;
constexpr int Bb = 4;
constexpr int Ee = 64;
}

__global__ __launch_bounds__(256, 4) void sparse_attn_kernel(
    const float* __restrict__ Q,
    const float* __restrict__ Kp,
    const float* __restrict__ Vp,
    float*       __restrict__ O)
{
    const unsigned FULL = 0xffffffffu;
    const int offsB[8] = {9,13,21,37,69,133,261,517};

    const int warp   = threadIdx.x >> 5;
    const int lane   = threadIdx.x & 31;
    const int lane16 = lane & 15;
    const int sub    = lane >> 4;                      // 0: query lA, 1: query lA+1
    const int gbase  = blockIdx.x * 16 + warp * 2;     // query id of sub=0
    const int g      = gbase + sub;

    const int l  = g & (Lq - 1);
    const int lA = gbase & (Lq - 1);                   // warp-uniform base position
    const int bh = g >> 11;
    const int h  = bh & (Hh - 1);
    const int b  = bh >> 3;

    const int rowstride = Hh * Ee;                     // 512 floats
    const int rs4       = rowstride / 4;
    const int base_bh   = b * Lq * rowstride + h * Ee;
    const int qoff      = base_bh + l * rowstride;

    const float4* kbase = reinterpret_cast<const float4*>(Kp + base_bh) + lane16;
    const float4* vbase = reinterpret_cast<const float4*>(Vp + base_bh) + lane16;

    const float4 q = reinterpret_cast<const float4*>(Q + qoff)[lane16];

    float a;        // reduced window half-sum
    float s16;      // offset-1029 score

    // ---- K batch A: shared window union rows lA+1-i, i=0..8 (both halves
    //      load identical addresses -> 2 wavefronts per LDG) ----
    {
        float4 kw[9];
#pragma unroll
        for (int i = 0; i < 9; ++i) {
            int r = lA + 1 - i; r = r >= 0 ? r : 0;
            kw[i] = kbase[r * rs4];
        }
        float d[9];
#pragma unroll
        for (int i = 0; i < 9; ++i) {
            float t = q.x * kw[i].x;
            t = fmaf(q.y, kw[i].y, t);
            t = fmaf(q.z, kw[i].z, t);
            d[i] = fmaf(q.w, kw[i].w, t);
        }
        // per-half window partials: offset j -> row l-j = lA+1-(j+1-sub)
        float p[8];
#pragma unroll
        for (int j = 0; j < 8; ++j)
            p[j] = sub ? d[j] : d[j + 1];

        // halving tree masks 4,2,1 -> half-sum of window score (lane16&7)
        const bool b2 = lane16 & 4;
#pragma unroll
        for (int i = 0; i < 4; ++i) {
            const float send = b2 ? p[i] : p[i + 4];
            const float r    = __shfl_xor_sync(FULL, send, 4);
            p[i] = (b2 ? p[i + 4] : p[i]) + r;
        }
        const bool b1 = lane16 & 2;
#pragma unroll
        for (int i = 0; i < 2; ++i) {
            const float send = b1 ? p[i] : p[i + 2];
            const float r    = __shfl_xor_sync(FULL, send, 2);
            p[i] = (b1 ? p[i + 2] : p[i]) + r;
        }
        const bool b0 = lane16 & 1;
        const float send = b0 ? p[0] : p[1];
        const float r    = __shfl_xor_sync(FULL, send, 1);
        a = (b0 ? p[1] : p[0]) + r;
    }

    // ---- K batch B: per-half log rows (8) + offset-1029 row ----
    float bb;
    {
        float4 kb[9];
#pragma unroll
        for (int j = 0; j < 8; ++j) {
            int k = l - offsB[j]; k = k >= 0 ? k : 0;
            kb[j] = kbase[k * rs4];
        }
        {
            int k = l - 1029; k = k >= 0 ? k : 0;
            kb[8] = kbase[k * rs4];
        }
        float pb[8];
#pragma unroll
        for (int j = 0; j < 8; ++j) {
            float t = q.x * kb[j].x;
            t = fmaf(q.y, kb[j].y, t);
            t = fmaf(q.z, kb[j].z, t);
            pb[j] = fmaf(q.w, kb[j].w, t);
        }
        {
            float t = q.x * kb[8].x;
            t = fmaf(q.y, kb[8].y, t);
            t = fmaf(q.z, kb[8].z, t);
            s16 = fmaf(q.w, kb[8].w, t);
        }
#pragma unroll
        for (int m = 8; m; m >>= 1)
            s16 += __shfl_xor_sync(FULL, s16, m);

        const bool b2 = lane16 & 4;
#pragma unroll
        for (int i = 0; i < 4; ++i) {
            const float send = b2 ? pb[i] : pb[i + 4];
            const float r    = __shfl_xor_sync(FULL, send, 4);
            pb[i] = (b2 ? pb[i + 4] : pb[i]) + r;
        }
        const bool b1 = lane16 & 2;
#pragma unroll
        for (int i = 0; i < 2; ++i) {
            const float send = b1 ? pb[i] : pb[i + 2];
            const float r    = __shfl_xor_sync(FULL, send, 2);
            pb[i] = (b1 ? pb[i + 2] : pb[i]) + r;
        }
        const bool b0 = lane16 & 1;
        const float send = b0 ? pb[0] : pb[1];
        const float r    = __shfl_xor_sync(FULL, send, 1);
        bb = (b0 ? pb[1] : pb[0]) + r;
    }

    // ---- merge halves: lane j (0..15) ends with full score j ----
    float sc;
    {
        const bool hi = lane16 & 8;
        const float send = hi ? a : bb;
        const float r    = __shfl_xor_sync(FULL, send, 8);
        sc = (hi ? bb : a) + r;
    }

    // ---- lane-parallel softmax, no max-subtraction (|s| <~ 6, fp32-safe) ----
    int my_off;
    {
        const int lo[16] = {0,1,2,3,4,5,6,7,9,13,21,37,69,133,261,517};
        my_off = lo[lane16];
    }
    float w = (l >= my_off) ? __expf(sc * 0.125f) : 0.f;
    const float w16 = (l >= 1029) ? __expf(s16 * 0.125f) : 0.f;

    float den = w;
#pragma unroll
    for (int m = 8; m; m >>= 1)
        den += __shfl_xor_sync(FULL, den, m);
    den += w16;
    const float inv = __fdividef(1.f, den);

    // ---- V batch 1: shared window union rows (2 wf per LDG) ----
    float4 acc = make_float4(0.f, 0.f, 0.f, 0.f);
    {
        float4 vw[9];
#pragma unroll
        for (int i = 0; i < 9; ++i) {
            int r = lA + 1 - i; r = r >= 0 ? r : 0;
            vw[i] = vbase[r * rs4];
        }
#pragma unroll
        for (int i = 0; i < 9; ++i) {
            // row lA+1-i corresponds to this half's window offset j = i-1+sub
            const int jj = i - 1 + sub;
            float wj = __shfl_sync(FULL, w, jj & 7, 16);
            wj = ((unsigned)jj < 8u) ? wj : 0.f;
            acc.x = fmaf(wj, vw[i].x, acc.x);
            acc.y = fmaf(wj, vw[i].y, acc.y);
            acc.z = fmaf(wj, vw[i].z, acc.z);
            acc.w = fmaf(wj, vw[i].w, acc.w);
        }
    }
    // ---- V batch 2: per-half log rows (8) + offset-1029 row ----
    {
        float4 vb[9];
#pragma unroll
        for (int j = 0; j < 8; ++j) {
            int k = l - offsB[j]; k = k >= 0 ? k : 0;
            vb[j] = vbase[k * rs4];
        }
        {
            int k = l - 1029; k = k >= 0 ? k : 0;
            vb[8] = vbase[k * rs4];
        }
#pragma unroll
        for (int j = 0; j < 8; ++j) {
            const float wj = __shfl_sync(FULL, w, 8 + j, 16);
            acc.x = fmaf(wj, vb[j].x, acc.x);
            acc.y = fmaf(wj, vb[j].y, acc.y);
            acc.z = fmaf(wj, vb[j].z, acc.z);
            acc.w = fmaf(wj, vb[j].w, acc.w);
        }
        acc.x = fmaf(w16, vb[8].x, acc.x);
        acc.y = fmaf(w16, vb[8].y, acc.y);
        acc.z = fmaf(w16, vb[8].z, acc.z);
        acc.w = fmaf(w16, vb[8].w, acc.w);
    }

    float4 out;
    out.x = acc.x * inv;
    out.y = acc.y * inv;
    out.z = acc.z * inv;
    out.w = acc.w * inv;
    reinterpret_cast<float4*>(O + qoff)[lane16] = out;
}

extern "C" void kernel_launch(void* const* d_in, const int* in_sizes, int n_in,
                              void* d_out, int out_size)
{
    const float* Q = (const float*)d_in[0];
    const float* K = (const float*)d_in[1];
    const float* V = (const float*)d_in[2];
    float*       O = (float*)d_out;

    const int total_queries = Bb * Hh * Lq;            // 65536
    dim3 grid(total_queries / 16);
    dim3 block(256);
    sparse_attn_kernel<<<grid, block>>>(Q, K, V, O);
}